// round 3
// baseline (speedup 1.0000x reference)
#include <cuda_runtime.h>
#include <math.h>

#define PI_F 3.14159265358979323846f

constexpr int TB = 64;        // points per block
constexpr int NTHREADS = 256;
constexpr int GC = 2052;      // grid cols (2048 + NS - 1)

struct SmemLayout {
  float a512[512 * TB];   // layer3 output
  float b256[256 * TB];   // layer2/4 outputs, then logits [75][64]
  float c64[64 * TB];     // layer1/5 outputs
  float pos[2 * TB];      // input positions [2][64]
};

// Generic fused layer: sOut[N][TB] = act(W^T sIn + b), activations SMEM-resident,
// weights streamed from L2 via __ldg. Thread tile: 4 points x RN neurons.
template <int K, int N, bool RELU>
__device__ __forceinline__ void mlp_layer(const float* __restrict__ W,
                                          const float* __restrict__ bias,
                                          const float* __restrict__ sIn,
                                          float* __restrict__ sOut, int tid) {
  const int tm = (tid & 15) * 4;   // point base (0..60)
  const int tn = tid >> 4;         // 0..15
  constexpr int RN = (N >= 128) ? 8 : 4;
  constexpr int NCHUNK = N / (16 * RN);
#pragma unroll
  for (int c = 0; c < NCHUNK; ++c) {
    const int n0 = (tn + 16 * c) * RN;
    float acc[4][RN];
#pragma unroll
    for (int i = 0; i < 4; ++i)
#pragma unroll
      for (int j = 0; j < RN; ++j) acc[i][j] = 0.0f;

#pragma unroll 4
    for (int k = 0; k < K; ++k) {
      const float4 a = *reinterpret_cast<const float4*>(sIn + k * TB + tm);
      const float* wr = W + k * N + n0;
      float w[RN];
      const float4 w0 = __ldg(reinterpret_cast<const float4*>(wr));
      w[0] = w0.x; w[1] = w0.y; w[2] = w0.z; w[3] = w0.w;
      if constexpr (RN == 8) {
        const float4 w1 = __ldg(reinterpret_cast<const float4*>(wr + 4));
        w[4] = w1.x; w[5] = w1.y; w[6] = w1.z; w[7] = w1.w;
      }
#pragma unroll
      for (int j = 0; j < RN; ++j) {
        acc[0][j] = fmaf(a.x, w[j], acc[0][j]);
        acc[1][j] = fmaf(a.y, w[j], acc[1][j]);
        acc[2][j] = fmaf(a.z, w[j], acc[2][j]);
        acc[3][j] = fmaf(a.w, w[j], acc[3][j]);
      }
    }
#pragma unroll
    for (int j = 0; j < RN; ++j) {
      const float bb = __ldg(bias + n0 + j);
      float4 o;
      o.x = acc[0][j] + bb;
      o.y = acc[1][j] + bb;
      o.z = acc[2][j] + bb;
      o.w = acc[3][j] + bb;
      if (RELU) {
        o.x = fmaxf(o.x, 0.0f); o.y = fmaxf(o.y, 0.0f);
        o.z = fmaxf(o.z, 0.0f); o.w = fmaxf(o.w, 0.0f);
      }
      *reinterpret_cast<float4*>(sOut + (n0 + j) * TB + tm) = o;
    }
  }
}

__global__ __launch_bounds__(NTHREADS, 1) void gridnet_kernel(
    const float* __restrict__ pos, const float* __restrict__ grid_pos,
    const float* __restrict__ w1, const float* __restrict__ b1,
    const float* __restrict__ w2, const float* __restrict__ b2,
    const float* __restrict__ w3, const float* __restrict__ b3,
    const float* __restrict__ w4, const float* __restrict__ b4,
    const float* __restrict__ w5, const float* __restrict__ b5,
    const float* __restrict__ w6, const float* __restrict__ b6,
    float* __restrict__ out) {
  extern __shared__ float smem_raw[];
  SmemLayout& S = *reinterpret_cast<SmemLayout*>(smem_raw);
  const int tid = threadIdx.x;
  const int base = blockIdx.x * TB;

  // Load positions, transposed to [component][point]
  if (tid < 2 * TB) {
    const float v = pos[base * 2 + tid];
    S.pos[(tid & 1) * TB + (tid >> 1)] = v;
  }
  __syncthreads();

  mlp_layer<2, 64, true>(w1, b1, S.pos, S.c64, tid);
  __syncthreads();
  mlp_layer<64, 256, true>(w2, b2, S.c64, S.b256, tid);
  __syncthreads();
  mlp_layer<256, 512, true>(w3, b3, S.b256, S.a512, tid);
  __syncthreads();
  mlp_layer<512, 256, true>(w4, b4, S.a512, S.b256, tid);
  __syncthreads();
  mlp_layer<256, 64, true>(w5, b5, S.b256, S.c64, tid);
  __syncthreads();

  // Layer 6: 64 -> 75 logits (no relu), store into S.b256 as [75][TB]
  {
    const int m = tid & 63;
    const int g = tid >> 6;  // 4 groups, n strided by 4
    for (int n = g; n < 75; n += 4) {
      float acc = __ldg(b6 + n);
      const float* wcol = w6 + n;
      float partial = 0.0f;
#pragma unroll 8
      for (int k = 0; k < 64; ++k)
        partial = fmaf(S.c64[k * TB + m], __ldg(wcol + k * 75), partial);
      S.b256[n * TB + m] = acc + partial;
    }
  }
  __syncthreads();

  // Epilogue: softmax over 75, fused with 5x5x3 gather, sigmoid, threshold
  if (tid < TB) {
    const int m = tid;
    const float p0 = S.pos[m];
    const float p1 = S.pos[TB + m];

    float mx = -1e30f;
    for (int n = 0; n < 75; ++n) mx = fmaxf(mx, S.b256[n * TB + m]);

    const float gx = p0 / PI_F * 1023.0f;
    const float gy = (p1 + PI_F) / (2.0f * PI_F) * 2047.0f;
    // ix = int(gx) + OFFSET - HALF + r = int(gx) + r  (OFFSET == HALF == 2)
    const int tlx = (int)gx;
    const int tly = (int)gy;

    float sum = 0.0f;
    float acc[3] = {0.0f, 0.0f, 0.0f};
    int n = 0;
#pragma unroll
    for (int f = 0; f < 3; ++f) {
      float a = 0.0f;
#pragma unroll
      for (int r = 0; r < 5; ++r) {
        const float* gp = grid_pos + ((size_t)(tlx + r) * GC + tly) * 3 + f;
#pragma unroll
        for (int cc = 0; cc < 5; ++cc) {
          const float e = __expf(S.b256[n * TB + m] - mx);
          sum += e;
          a = fmaf(e, __ldg(gp + cc * 3), a);
          ++n;
        }
      }
      acc[f] = a;
    }
    const float inv = 1.0f / sum;
    const int g = base + m;
#pragma unroll
    for (int f = 0; f < 3; ++f) {
      const float x = acc[f] * inv;
      float s = 1.0f / (1.0f + __expf(-x));
      s = (s > 0.1f) ? s : 0.0f;
      out[g * 3 + f] = s * 255.0f;
    }
  }
}

extern "C" void kernel_launch(void* const* d_in, const int* in_sizes, int n_in,
                              void* d_out, int out_size) {
  const float* pos      = (const float*)d_in[0];
  const float* grid_pos = (const float*)d_in[1];
  const float* w1 = (const float*)d_in[2];
  const float* b1 = (const float*)d_in[3];
  const float* w2 = (const float*)d_in[4];
  const float* b2 = (const float*)d_in[5];
  const float* w3 = (const float*)d_in[6];
  const float* b3 = (const float*)d_in[7];
  const float* w4 = (const float*)d_in[8];
  const float* b4 = (const float*)d_in[9];
  const float* w5 = (const float*)d_in[10];
  const float* b5 = (const float*)d_in[11];
  const float* w6 = (const float*)d_in[12];
  const float* b6 = (const float*)d_in[13];
  float* out = (float*)d_out;

  const int B = in_sizes[0] / 2;
  const int blocks = B / TB;
  const size_t smem = sizeof(SmemLayout);

  cudaFuncSetAttribute(gridnet_kernel,
                       cudaFuncAttributeMaxDynamicSharedMemorySize, (int)smem);
  gridnet_kernel<<<blocks, NTHREADS, smem>>>(
      pos, grid_pos, w1, b1, w2, b2, w3, b3, w4, b4, w5, b5, w6, b6, out);
}

// round 6
// speedup vs baseline: 1.0009x; 1.0009x over previous
#include <cuda_runtime.h>
#include <math.h>

#define PI_F 3.14159265358979323846f

constexpr int TB = 64;        // points per block
constexpr int NTHREADS = 256;
constexpr int GC = 2052;      // grid cols (2048 + NS - 1)

struct SmemLayout {
  float a512[512 * TB];   // layer3 output
  float b256[256 * TB];   // layer2/4 outputs, then logits [75][64]
  float c64[64 * TB];     // layer1/5 outputs
  float pos[2 * TB];      // input positions [2][64]
};

// Generic fused layer: sOut[N][TB] = act(W^T sIn + b), activations SMEM-resident,
// weights streamed from L2 via __ldg. Thread tile: 4 points x RN neurons.
template <int K, int N, bool RELU>
__device__ __forceinline__ void mlp_layer(const float* __restrict__ W,
                                          const float* __restrict__ bias,
                                          const float* __restrict__ sIn,
                                          float* __restrict__ sOut, int tid) {
  const int tm = (tid & 15) * 4;   // point base (0..60)
  const int tn = tid >> 4;         // 0..15
  constexpr int RN = (N >= 128) ? 8 : 4;
  constexpr int NCHUNK = N / (16 * RN);
#pragma unroll
  for (int c = 0; c < NCHUNK; ++c) {
    const int n0 = (tn + 16 * c) * RN;
    float acc[4][RN];
#pragma unroll
    for (int i = 0; i < 4; ++i)
#pragma unroll
      for (int j = 0; j < RN; ++j) acc[i][j] = 0.0f;

#pragma unroll 4
    for (int k = 0; k < K; ++k) {
      const float4 a = *reinterpret_cast<const float4*>(sIn + k * TB + tm);
      const float* wr = W + k * N + n0;
      float w[RN];
      const float4 w0 = __ldg(reinterpret_cast<const float4*>(wr));
      w[0] = w0.x; w[1] = w0.y; w[2] = w0.z; w[3] = w0.w;
      if constexpr (RN == 8) {
        const float4 w1 = __ldg(reinterpret_cast<const float4*>(wr + 4));
        w[4] = w1.x; w[5] = w1.y; w[6] = w1.z; w[7] = w1.w;
      }
#pragma unroll
      for (int j = 0; j < RN; ++j) {
        acc[0][j] = fmaf(a.x, w[j], acc[0][j]);
        acc[1][j] = fmaf(a.y, w[j], acc[1][j]);
        acc[2][j] = fmaf(a.z, w[j], acc[2][j]);
        acc[3][j] = fmaf(a.w, w[j], acc[3][j]);
      }
    }
#pragma unroll
    for (int j = 0; j < RN; ++j) {
      const float bb = __ldg(bias + n0 + j);
      float4 o;
      o.x = acc[0][j] + bb;
      o.y = acc[1][j] + bb;
      o.z = acc[2][j] + bb;
      o.w = acc[3][j] + bb;
      if (RELU) {
        o.x = fmaxf(o.x, 0.0f); o.y = fmaxf(o.y, 0.0f);
        o.z = fmaxf(o.z, 0.0f); o.w = fmaxf(o.w, 0.0f);
      }
      *reinterpret_cast<float4*>(sOut + (n0 + j) * TB + tm) = o;
    }
  }
}

__global__ __launch_bounds__(NTHREADS, 1) void gridnet_kernel(
    const float* __restrict__ pos, const float* __restrict__ grid_pos,
    const float* __restrict__ w1, const float* __restrict__ b1,
    const float* __restrict__ w2, const float* __restrict__ b2,
    const float* __restrict__ w3, const float* __restrict__ b3,
    const float* __restrict__ w4, const float* __restrict__ b4,
    const float* __restrict__ w5, const float* __restrict__ b5,
    const float* __restrict__ w6, const float* __restrict__ b6,
    float* __restrict__ out) {
  extern __shared__ float smem_raw[];
  SmemLayout& S = *reinterpret_cast<SmemLayout*>(smem_raw);
  const int tid = threadIdx.x;
  const int base = blockIdx.x * TB;

  // Load positions, transposed to [component][point]
  if (tid < 2 * TB) {
    const float v = pos[base * 2 + tid];
    S.pos[(tid & 1) * TB + (tid >> 1)] = v;
  }
  __syncthreads();

  mlp_layer<2, 64, true>(w1, b1, S.pos, S.c64, tid);
  __syncthreads();
  mlp_layer<64, 256, true>(w2, b2, S.c64, S.b256, tid);
  __syncthreads();
  mlp_layer<256, 512, true>(w3, b3, S.b256, S.a512, tid);
  __syncthreads();
  mlp_layer<512, 256, true>(w4, b4, S.a512, S.b256, tid);
  __syncthreads();
  mlp_layer<256, 64, true>(w5, b5, S.b256, S.c64, tid);
  __syncthreads();

  // Layer 6: 64 -> 75 logits (no relu), store into S.b256 as [75][TB]
  {
    const int m = tid & 63;
    const int g = tid >> 6;  // 4 groups, n strided by 4
    for (int n = g; n < 75; n += 4) {
      float acc = __ldg(b6 + n);
      const float* wcol = w6 + n;
      float partial = 0.0f;
#pragma unroll 8
      for (int k = 0; k < 64; ++k)
        partial = fmaf(S.c64[k * TB + m], __ldg(wcol + k * 75), partial);
      S.b256[n * TB + m] = acc + partial;
    }
  }
  __syncthreads();

  // Epilogue: softmax over 75, fused with 5x5x3 gather, sigmoid, threshold
  if (tid < TB) {
    const int m = tid;
    const float p0 = S.pos[m];
    const float p1 = S.pos[TB + m];

    float mx = -1e30f;
    for (int n = 0; n < 75; ++n) mx = fmaxf(mx, S.b256[n * TB + m]);

    const float gx = p0 / PI_F * 1023.0f;
    const float gy = (p1 + PI_F) / (2.0f * PI_F) * 2047.0f;
    // ix = int(gx) + OFFSET - HALF + r = int(gx) + r  (OFFSET == HALF == 2)
    const int tlx = (int)gx;
    const int tly = (int)gy;

    float sum = 0.0f;
    float acc[3] = {0.0f, 0.0f, 0.0f};
    int n = 0;
#pragma unroll
    for (int f = 0; f < 3; ++f) {
      float a = 0.0f;
#pragma unroll
      for (int r = 0; r < 5; ++r) {
        const float* gp = grid_pos + ((size_t)(tlx + r) * GC + tly) * 3 + f;
#pragma unroll
        for (int cc = 0; cc < 5; ++cc) {
          const float e = __expf(S.b256[n * TB + m] - mx);
          sum += e;
          a = fmaf(e, __ldg(gp + cc * 3), a);
          ++n;
        }
      }
      acc[f] = a;
    }
    const float inv = 1.0f / sum;
    const int g = base + m;
#pragma unroll
    for (int f = 0; f < 3; ++f) {
      const float x = acc[f] * inv;
      float s = 1.0f / (1.0f + __expf(-x));
      s = (s > 0.1f) ? s : 0.0f;
      out[g * 3 + f] = s * 255.0f;
    }
  }
}

extern "C" void kernel_launch(void* const* d_in, const int* in_sizes, int n_in,
                              void* d_out, int out_size) {
  const float* pos      = (const float*)d_in[0];
  const float* grid_pos = (const float*)d_in[1];
  const float* w1 = (const float*)d_in[2];
  const float* b1 = (const float*)d_in[3];
  const float* w2 = (const float*)d_in[4];
  const float* b2 = (const float*)d_in[5];
  const float* w3 = (const float*)d_in[6];
  const float* b3 = (const float*)d_in[7];
  const float* w4 = (const float*)d_in[8];
  const float* b4 = (const float*)d_in[9];
  const float* w5 = (const float*)d_in[10];
  const float* b5 = (const float*)d_in[11];
  const float* w6 = (const float*)d_in[12];
  const float* b6 = (const float*)d_in[13];
  float* out = (float*)d_out;

  const int B = in_sizes[0] / 2;
  const int blocks = B / TB;
  const size_t smem = sizeof(SmemLayout);

  cudaFuncSetAttribute(gridnet_kernel,
                       cudaFuncAttributeMaxDynamicSharedMemorySize, (int)smem);
  gridnet_kernel<<<blocks, NTHREADS, smem>>>(
      pos, grid_pos, w1, b1, w2, b2, w3, b3, w4, b4, w5, b5, w6, b6, out);
}

// round 7
// speedup vs baseline: 10.3294x; 10.3201x over previous
#include <cuda_runtime.h>
#include <cuda_bf16.h>
#include <math.h>
#include <stdint.h>

#define PI_F 3.14159265358979323846f
constexpr int GC = 2052;

// bf16 weights, fragment-major (written by prep kernel each launch)
__device__ __align__(16) unsigned char g_wt[606208];
constexpr int WOFF2 = 0;        // K=64  Np=256
constexpr int WOFF3 = 32768;    // K=256 Np=512
constexpr int WOFF4 = 294912;   // K=512 Np=256
constexpr int WOFF5 = 557056;   // K=256 Np=64
constexpr int WOFF6 = 589824;   // K=64  Np=128 (75 valid)

__device__ __forceinline__ uint32_t s2u(const void* p) {
  uint32_t a;
  asm("{ .reg .u64 t; cvta.to.shared.u64 t, %1; cvt.u32.u64 %0, t; }" : "=r"(a) : "l"(p));
  return a;
}

// fp32 [K][Ntrue] -> bf16 fragment-major: per (np,kt) 512B block = 32 lanes x 16B,
// lane 16B = {b0,b1 of n-tile0, b0,b1 of n-tile1}, each reg = 2 bf16 (low k first)
__global__ void prep(const float* __restrict__ w2, const float* __restrict__ w3,
                     const float* __restrict__ w4, const float* __restrict__ w5,
                     const float* __restrict__ w6) {
  int i = blockIdx.x * blockDim.x + threadIdx.x;
  const float* src; int K, Nt, off, base;
  if (i < 16384)       { src = w2; K = 64;  Nt = 256; off = WOFF2; base = 0; }
  else if (i < 147456) { src = w3; K = 256; Nt = 512; off = WOFF3; base = 16384; }
  else if (i < 278528) { src = w4; K = 512; Nt = 256; off = WOFF4; base = 147456; }
  else if (i < 294912) { src = w5; K = 256; Nt = 64;  off = WOFF5; base = 278528; }
  else if (i < 303104) { src = w6; K = 64;  Nt = 75;  off = WOFF6; base = 294912; }
  else return;
  int e = i - base;
  int h = e & 1, r = (e >> 1) & 3, lane = (e >> 3) & 31, t = e >> 8;
  int KT = K >> 4;
  int kt = t % KT, np = t / KT;
  int n = np * 16 + (r >> 1) * 8 + (lane >> 2);
  int k = kt * 16 + (lane & 3) * 2 + (r & 1) * 8 + h;
  float v = (n < Nt) ? src[k * Nt + n] : 0.0f;
  *reinterpret_cast<__nv_bfloat16*>(g_wt + off + e * 2) = __float2bfloat16(v);
}

#define MMA16816(d, a0, a1, a2, a3, b0, b1)                                   \
  asm volatile(                                                               \
      "mma.sync.aligned.m16n8k16.row.col.f32.bf16.bf16.f32 "                  \
      "{%0,%1,%2,%3}, {%4,%5,%6,%7}, {%8,%9}, {%0,%1,%2,%3};"                 \
      : "+f"((d)[0]), "+f"((d)[1]), "+f"((d)[2]), "+f"((d)[3])                \
      : "r"(a0), "r"(a1), "r"(a2), "r"(a3), "r"(b0), "r"(b1))

// One MLP layer on tensor cores. In: bf16 swizzled [128][K]; Out: bf16 swizzled
// [128][Np] (relu) or f32 logits [128][80] (LOGITS). Warp (wm,wn): 64 rows x Np/4.
template <int K, int Np, bool LOGITS>
__device__ __forceinline__ void mma_layer(const unsigned char* __restrict__ Wg,
                                          const float* __restrict__ sBias,
                                          const unsigned char* __restrict__ sIn,
                                          unsigned char* __restrict__ sOut,
                                          int lane, int wm, int wn) {
  constexpr int KT = K / 16, P = Np / 64, RBI = 2 * K;
  const int sw = (lane & 7) << 4;
  const int rowbase = (wm * 64 + (lane & 7) + ((lane & 8) ? 8 : 0)) * RBI;
  const int koff = (lane & 16) ? 16 : 0;
  const int ssw = ((lane >> 2) & 7) << 4;
  const int srow0 = wm * 64 + (lane >> 2);
  const int scol = (lane & 3) * 2;
  const uint32_t inb = s2u(sIn);

  for (int p = 0; p < P; ++p) {
    const int npg = wn * P + p;
    float acc[4][2][4];
#pragma unroll
    for (int mt = 0; mt < 4; ++mt)
#pragma unroll
      for (int nt = 0; nt < 2; ++nt)
#pragma unroll
        for (int q = 0; q < 4; ++q) acc[mt][nt][q] = 0.0f;

    const unsigned char* wp = Wg + (size_t)npg * KT * 512 + lane * 16;
#pragma unroll 4
    for (int kt = 0; kt < KT; ++kt) {
      const uint4 b = *reinterpret_cast<const uint4*>(wp + kt * 512);
      const int kb = (kt * 32 + koff) ^ sw;
#pragma unroll
      for (int mt = 0; mt < 4; ++mt) {
        uint32_t a0, a1, a2, a3;
        asm volatile("ldmatrix.sync.aligned.m8n8.x4.shared.b16 {%0,%1,%2,%3}, [%4];"
                     : "=r"(a0), "=r"(a1), "=r"(a2), "=r"(a3)
                     : "r"(inb + rowbase + mt * 16 * RBI + kb));
        MMA16816(acc[mt][0], a0, a1, a2, a3, b.x, b.y);
        MMA16816(acc[mt][1], a0, a1, a2, a3, b.z, b.w);
      }
    }
#pragma unroll
    for (int mt = 0; mt < 4; ++mt)
#pragma unroll
      for (int nt = 0; nt < 2; ++nt) {
        const int c = npg * 16 + nt * 8 + scol;
        const int r = srow0 + mt * 16;
        float d0 = acc[mt][nt][0] + sBias[c];
        float d1 = acc[mt][nt][1] + sBias[c + 1];
        float d2 = acc[mt][nt][2] + sBias[c];
        float d3 = acc[mt][nt][3] + sBias[c + 1];
        if (LOGITS) {
          float* lg = (float*)sOut;
          if (c < 75)     { lg[r * 80 + c]       = d0; lg[(r + 8) * 80 + c]     = d2; }
          if (c + 1 < 75) { lg[r * 80 + c + 1]   = d1; lg[(r + 8) * 80 + c + 1] = d3; }
        } else {
          d0 = fmaxf(d0, 0.0f); d1 = fmaxf(d1, 0.0f);
          d2 = fmaxf(d2, 0.0f); d3 = fmaxf(d3, 0.0f);
          uint32_t p0, p1;
          asm("cvt.rn.bf16x2.f32 %0, %1, %2;" : "=r"(p0) : "f"(d1), "f"(d0));
          asm("cvt.rn.bf16x2.f32 %0, %1, %2;" : "=r"(p1) : "f"(d3), "f"(d2));
          const int cb = (2 * c) ^ ssw;
          *(uint32_t*)(sOut + r * (2 * Np) + cb)       = p0;
          *(uint32_t*)(sOut + (r + 8) * (2 * Np) + cb) = p1;
        }
      }
  }
}

// smem: bias 4864 | pos 1024 | actC 16K | actB 64K | actA 128K  = 218880 B
constexpr int OFF_POS = 4864, OFF_C = 5888, OFF_B = 22272, OFF_A = 87808;
constexpr int SMEM_TOTAL = 218880;

__global__ __launch_bounds__(256, 1) void gridnet_mma(
    const float* __restrict__ pos, const float* __restrict__ grid_pos,
    const float* __restrict__ w1, const float* __restrict__ b1,
    const float* __restrict__ b2, const float* __restrict__ b3,
    const float* __restrict__ b4, const float* __restrict__ b5,
    const float* __restrict__ b6, float* __restrict__ out) {
  extern __shared__ unsigned char sm[];
  float* sBias = (float*)sm;
  float2* sPos = (float2*)(sm + OFF_POS);
  unsigned char* actC = sm + OFF_C;
  unsigned char* actB = sm + OFF_B;
  unsigned char* actA = sm + OFF_A;
  const int tid = threadIdx.x, lane = tid & 31, wid = tid >> 5;
  const int wm = wid & 1, wn = wid >> 1;
  const int base = blockIdx.x * 128;

  sBias[tid] = b2[tid];
  for (int i = 0; i < 2; ++i) sBias[256 + tid + i * 256] = b3[tid + i * 256];
  sBias[768 + tid] = b4[tid];
  if (tid < 64) sBias[1024 + tid] = b5[tid];
  if (tid < 75) sBias[1088 + tid] = b6[tid];
  else if (tid < 128) sBias[1088 + tid] = 0.0f;
  if (tid < 128) sPos[tid] = ((const float2*)pos)[base + tid];
  __syncthreads();

  // Layer 1 (2->64) fp32 cores, bf16 swizzled out
  {
    const int pt = tid >> 1, half = tid & 1;
    const float px = sPos[pt].x, py = sPos[pt].y;
    const int swz = (pt & 7) << 4;
    unsigned char* rowp = actC + pt * 128;
#pragma unroll
    for (int jj = 0; jj < 16; ++jj) {
      const int j = half * 32 + jj * 2;
      float h0 = fmaxf(fmaf(px, __ldg(w1 + j),     fmaf(py, __ldg(w1 + 64 + j),     __ldg(b1 + j))),     0.0f);
      float h1 = fmaxf(fmaf(px, __ldg(w1 + j + 1), fmaf(py, __ldg(w1 + 64 + j + 1), __ldg(b1 + j + 1))), 0.0f);
      uint32_t pk;
      asm("cvt.rn.bf16x2.f32 %0, %1, %2;" : "=r"(pk) : "f"(h1), "f"(h0));
      *(uint32_t*)(rowp + ((2 * j) ^ swz)) = pk;
    }
  }
  __syncthreads();
  mma_layer<64, 256, false>(g_wt + WOFF2, sBias,        actC, actB, lane, wm, wn);
  __syncthreads();
  mma_layer<256, 512, false>(g_wt + WOFF3, sBias + 256, actB, actA, lane, wm, wn);
  __syncthreads();
  mma_layer<512, 256, false>(g_wt + WOFF4, sBias + 768, actA, actB, lane, wm, wn);
  __syncthreads();
  mma_layer<256, 64, false>(g_wt + WOFF5, sBias + 1024, actB, actC, lane, wm, wn);
  __syncthreads();
  mma_layer<64, 128, true>(g_wt + WOFF6, sBias + 1088,  actC, actB, lane, wm, wn);
  __syncthreads();

  // softmax + gather + sigmoid epilogue (1 thread per point)
  if (tid < 128) {
    const float* L = (const float*)actB + tid * 80;
    float mx = -1e30f;
    for (int n = 0; n < 75; ++n) mx = fmaxf(mx, L[n]);
    const float px = sPos[tid].x, py = sPos[tid].y;
    const int tlx = (int)(px / PI_F * 1023.0f);
    const int tly = (int)((py + PI_F) / (2.0f * PI_F) * 2047.0f);
    float sum = 0.0f, accf[3];
    int n = 0;
#pragma unroll
    for (int f = 0; f < 3; ++f) {
      float a = 0.0f;
#pragma unroll
      for (int r = 0; r < 5; ++r) {
        const float* gp = grid_pos + ((size_t)(tlx + r) * GC + tly) * 3 + f;
#pragma unroll
        for (int cc = 0; cc < 5; ++cc) {
          const float e = __expf(L[n] - mx);
          sum += e;
          a = fmaf(e, __ldg(gp + cc * 3), a);
          ++n;
        }
      }
      accf[f] = a;
    }
    const float inv = 1.0f / sum;
    const int g = base + tid;
#pragma unroll
    for (int f = 0; f < 3; ++f) {
      const float x = accf[f] * inv;
      const float s = 1.0f / (1.0f + __expf(-x));
      out[g * 3 + f] = (s > 0.1f) ? s * 255.0f : 0.0f;
    }
  }
}

extern "C" void kernel_launch(void* const* d_in, const int* in_sizes, int n_in,
                              void* d_out, int out_size) {
  const float* pos      = (const float*)d_in[0];
  const float* grid_pos = (const float*)d_in[1];
  const float* w1 = (const float*)d_in[2];
  const float* b1 = (const float*)d_in[3];
  const float* w2 = (const float*)d_in[4];
  const float* b2 = (const float*)d_in[5];
  const float* w3 = (const float*)d_in[6];
  const float* b3 = (const float*)d_in[7];
  const float* w4 = (const float*)d_in[8];
  const float* b4 = (const float*)d_in[9];
  const float* w5 = (const float*)d_in[10];
  const float* b5 = (const float*)d_in[11];
  const float* w6 = (const float*)d_in[12];
  const float* b6 = (const float*)d_in[13];
  float* out = (float*)d_out;

  prep<<<(303104 + 255) / 256, 256>>>(w2, w3, w4, w5, w6);

  const int B = in_sizes[0] / 2;
  cudaFuncSetAttribute(gridnet_mma, cudaFuncAttributeMaxDynamicSharedMemorySize,
                       SMEM_TOTAL);
  gridnet_mma<<<B / 128, 256, SMEM_TOTAL>>>(pos, grid_pos, w1, b1, b2, b3, b4,
                                            b5, b6, out);
}

// round 9
// speedup vs baseline: 10.9177x; 1.0570x over previous
#include <cuda_runtime.h>
#include <cuda_bf16.h>
#include <math.h>
#include <stdint.h>

#define PI_F 3.14159265358979323846f
constexpr int GC = 2052;
constexpr int NTH = 512;

// bf16 weights, fragment-major (written by prep kernel each launch)
__device__ __align__(16) unsigned char g_wt[606208];
constexpr int WOFF2 = 0;        // K=64  Np=256
constexpr int WOFF3 = 32768;    // K=256 Np=512
constexpr int WOFF4 = 294912;   // K=512 Np=256
constexpr int WOFF5 = 557056;   // K=256 Np=64
constexpr int WOFF6 = 589824;   // K=64  Np=128 (75 valid)

__device__ __forceinline__ uint32_t s2u(const void* p) {
  uint32_t a;
  asm("{ .reg .u64 t; cvta.to.shared.u64 t, %1; cvt.u32.u64 %0, t; }" : "=r"(a) : "l"(p));
  return a;
}

// fp32 [K][Ntrue] -> bf16 fragment-major: per (np,kt) 512B block = 32 lanes x 16B,
// lane 16B = {b0,b1 of n-tile0, b0,b1 of n-tile1}, each reg = 2 bf16 (low k first)
__global__ void prep(const float* __restrict__ w2, const float* __restrict__ w3,
                     const float* __restrict__ w4, const float* __restrict__ w5,
                     const float* __restrict__ w6) {
  int i = blockIdx.x * blockDim.x + threadIdx.x;
  const float* src; int K, Nt, off, base;
  if (i < 16384)       { src = w2; K = 64;  Nt = 256; off = WOFF2; base = 0; }
  else if (i < 147456) { src = w3; K = 256; Nt = 512; off = WOFF3; base = 16384; }
  else if (i < 278528) { src = w4; K = 512; Nt = 256; off = WOFF4; base = 147456; }
  else if (i < 294912) { src = w5; K = 256; Nt = 64;  off = WOFF5; base = 278528; }
  else if (i < 303104) { src = w6; K = 64;  Nt = 75;  off = WOFF6; base = 294912; }
  else return;
  int e = i - base;
  int h = e & 1, r = (e >> 1) & 3, lane = (e >> 3) & 31, t = e >> 8;
  int KT = K >> 4;
  int kt = t % KT, np = t / KT;
  int n = np * 16 + (r >> 1) * 8 + (lane >> 2);
  int k = kt * 16 + (lane & 3) * 2 + (r & 1) * 8 + h;
  float v = (n < Nt) ? src[k * Nt + n] : 0.0f;
  *reinterpret_cast<__nv_bfloat16*>(g_wt + off + e * 2) = __float2bfloat16(v);
}

#define MMA16816(d, a0, a1, a2, a3, b0, b1)                                   \
  asm volatile(                                                               \
      "mma.sync.aligned.m16n8k16.row.col.f32.bf16.bf16.f32 "                  \
      "{%0,%1,%2,%3}, {%4,%5,%6,%7}, {%8,%9}, {%0,%1,%2,%3};"                 \
      : "+f"((d)[0]), "+f"((d)[1]), "+f"((d)[2]), "+f"((d)[3])                \
      : "r"(a0), "r"(a1), "r"(a2), "r"(a3), "r"(b0), "r"(b1))

// One MLP layer on tensor cores, 16 warps, warp grid WM(M) x (16/WM)(N).
// In: bf16 swizzled [128][K]; Out: bf16 swizzled [128][Np] (relu) or
// f32 logits [128][80] (LOGITS). Each warp: 128/WM rows x Np/(16/WM)*... cols.
template <int K, int Np, int WM, bool LOGITS>
__device__ __forceinline__ void mma_layer(const unsigned char* __restrict__ Wg,
                                          const float* __restrict__ sBias,
                                          const unsigned char* __restrict__ sIn,
                                          unsigned char* __restrict__ sOut,
                                          int lane, int wid) {
  constexpr int WN = 16 / WM;
  constexpr int MT = 128 / (16 * WM);   // m-tiles per warp
  constexpr int P  = Np / (16 * WN);    // n-chunks per warp
  constexpr int KT = K / 16, RBI = 2 * K;
  const int wm = wid & (WM - 1);
  const int wn = wid / WM;
  const int sw = (lane & 7) << 4;
  const int rowbase = (wm * 16 * MT + (lane & 7) + ((lane & 8) ? 8 : 0)) * RBI;
  const int koff = (lane & 16) ? 16 : 0;
  const int ssw = ((lane >> 2) & 7) << 4;
  const int srow0 = wm * 16 * MT + (lane >> 2);
  const int scol = (lane & 3) * 2;
  const uint32_t inb = s2u(sIn);

#pragma unroll
  for (int p = 0; p < P; ++p) {
    const int npg = wn * P + p;
    float acc[MT][2][4];
#pragma unroll
    for (int mt = 0; mt < MT; ++mt)
#pragma unroll
      for (int nt = 0; nt < 2; ++nt)
#pragma unroll
        for (int q = 0; q < 4; ++q) acc[mt][nt][q] = 0.0f;

    const unsigned char* wp = Wg + (size_t)npg * KT * 512 + lane * 16;
#pragma unroll 4
    for (int kt = 0; kt < KT; ++kt) {
      const uint4 b = *reinterpret_cast<const uint4*>(wp + kt * 512);
      const int kb = (kt * 32 + koff) ^ sw;
#pragma unroll
      for (int mt = 0; mt < MT; ++mt) {
        uint32_t a0, a1, a2, a3;
        asm volatile("ldmatrix.sync.aligned.m8n8.x4.shared.b16 {%0,%1,%2,%3}, [%4];"
                     : "=r"(a0), "=r"(a1), "=r"(a2), "=r"(a3)
                     : "r"(inb + rowbase + mt * 16 * RBI + kb));
        MMA16816(acc[mt][0], a0, a1, a2, a3, b.x, b.y);
        MMA16816(acc[mt][1], a0, a1, a2, a3, b.z, b.w);
      }
    }
#pragma unroll
    for (int mt = 0; mt < MT; ++mt)
#pragma unroll
      for (int nt = 0; nt < 2; ++nt) {
        const int c = npg * 16 + nt * 8 + scol;
        const int r = srow0 + mt * 16;
        float d0 = acc[mt][nt][0] + sBias[c];
        float d1 = acc[mt][nt][1] + sBias[c + 1];
        float d2 = acc[mt][nt][2] + sBias[c];
        float d3 = acc[mt][nt][3] + sBias[c + 1];
        if (LOGITS) {
          float* lg = (float*)sOut;
          if (c < 75)     { lg[r * 80 + c]       = d0; lg[(r + 8) * 80 + c]     = d2; }
          if (c + 1 < 75) { lg[r * 80 + c + 1]   = d1; lg[(r + 8) * 80 + c + 1] = d3; }
        } else {
          d0 = fmaxf(d0, 0.0f); d1 = fmaxf(d1, 0.0f);
          d2 = fmaxf(d2, 0.0f); d3 = fmaxf(d3, 0.0f);
          uint32_t p0, p1;
          asm("cvt.rn.bf16x2.f32 %0, %1, %2;" : "=r"(p0) : "f"(d1), "f"(d0));
          asm("cvt.rn.bf16x2.f32 %0, %1, %2;" : "=r"(p1) : "f"(d3), "f"(d2));
          const int cb = (2 * c) ^ ssw;
          *(uint32_t*)(sOut + r * (2 * Np) + cb)       = p0;
          *(uint32_t*)(sOut + (r + 8) * (2 * Np) + cb) = p1;
        }
      }
  }
}

// smem: bias 4864 | pos 1024 | actC 16K | actB 64K | actA 128K  = 218880 B
constexpr int OFF_POS = 4864, OFF_C = 5888, OFF_B = 22272, OFF_A = 87808;
constexpr int SMEM_TOTAL = 218880;

__global__ __launch_bounds__(NTH, 1) void gridnet_mma(
    const float* __restrict__ pos, const float* __restrict__ grid_pos,
    const float* __restrict__ w1, const float* __restrict__ b1,
    const float* __restrict__ b2, const float* __restrict__ b3,
    const float* __restrict__ b4, const float* __restrict__ b5,
    const float* __restrict__ b6, float* __restrict__ out) {
  extern __shared__ unsigned char sm[];
  float* sBias = (float*)sm;
  float2* sPos = (float2*)(sm + OFF_POS);
  unsigned char* actC = sm + OFF_C;
  unsigned char* actB = sm + OFF_B;
  unsigned char* actA = sm + OFF_A;
  const int tid = threadIdx.x, lane = tid & 31, wid = tid >> 5;
  const int base = blockIdx.x * 128;

  if (tid < 256) sBias[tid] = b2[tid];
  else sBias[tid] = b3[tid - 256];
  if (tid < 256) sBias[512 + tid] = b3[256 + tid];
  else sBias[512 + tid] = b4[tid - 256];
  if (tid < 64) sBias[1024 + tid] = b5[tid];
  else if (tid < 139) sBias[1024 + tid] = b6[tid - 64];
  else if (tid < 192) sBias[1024 + tid] = 0.0f;
  if (tid < 128) sPos[tid] = ((const float2*)pos)[base + tid];
  __syncthreads();

  // Layer 1 (2->64) fp32 cores, bf16 swizzled out; 4 threads per point
  {
    const int pt = tid >> 2, q = tid & 3;
    const float px = sPos[pt].x, py = sPos[pt].y;
    const int swz = (pt & 7) << 4;
    unsigned char* rowp = actC + pt * 128;
#pragma unroll
    for (int jj = 0; jj < 8; ++jj) {
      const int j = q * 16 + jj * 2;
      float h0 = fmaxf(fmaf(px, __ldg(w1 + j),     fmaf(py, __ldg(w1 + 64 + j),     __ldg(b1 + j))),     0.0f);
      float h1 = fmaxf(fmaf(px, __ldg(w1 + j + 1), fmaf(py, __ldg(w1 + 64 + j + 1), __ldg(b1 + j + 1))), 0.0f);
      uint32_t pk;
      asm("cvt.rn.bf16x2.f32 %0, %1, %2;" : "=r"(pk) : "f"(h1), "f"(h0));
      *(uint32_t*)(rowp + ((2 * j) ^ swz)) = pk;
    }
  }
  __syncthreads();
  mma_layer<64, 256, 2, false>(g_wt + WOFF2, sBias,        actC, actB, lane, wid);
  __syncthreads();
  mma_layer<256, 512, 2, false>(g_wt + WOFF3, sBias + 256, actB, actA, lane, wid);
  __syncthreads();
  mma_layer<512, 256, 2, false>(g_wt + WOFF4, sBias + 768, actA, actB, lane, wid);
  __syncthreads();
  mma_layer<256, 64, 4, false>(g_wt + WOFF5, sBias + 1024, actB, actC, lane, wid);
  __syncthreads();
  mma_layer<64, 128, 2, true>(g_wt + WOFF6, sBias + 1088,  actC, actB, lane, wid);
  __syncthreads();

  // softmax + gather + sigmoid epilogue (1 thread per point)
  if (tid < 128) {
    const float* L = (const float*)actB + tid * 80;
    float mx = -1e30f;
    for (int n = 0; n < 75; ++n) mx = fmaxf(mx, L[n]);
    const float px = sPos[tid].x, py = sPos[tid].y;
    const int tlx = (int)(px / PI_F * 1023.0f);
    const int tly = (int)((py + PI_F) / (2.0f * PI_F) * 2047.0f);
    float sum = 0.0f, accf[3];
    int n = 0;
#pragma unroll
    for (int f = 0; f < 3; ++f) {
      float a = 0.0f;
#pragma unroll
      for (int r = 0; r < 5; ++r) {
        const float* gp = grid_pos + ((size_t)(tlx + r) * GC + tly) * 3 + f;
#pragma unroll
        for (int cc = 0; cc < 5; ++cc) {
          const float e = __expf(L[n] - mx);
          sum += e;
          a = fmaf(e, __ldg(gp + cc * 3), a);
          ++n;
        }
      }
      accf[f] = a;
    }
    const float inv = 1.0f / sum;
    const int g = base + tid;
#pragma unroll
    for (int f = 0; f < 3; ++f) {
      const float x = accf[f] * inv;
      const float s = 1.0f / (1.0f + __expf(-x));
      out[g * 3 + f] = (s > 0.1f) ? s * 255.0f : 0.0f;
    }
  }
}

extern "C" void kernel_launch(void* const* d_in, const int* in_sizes, int n_in,
                              void* d_out, int out_size) {
  const float* pos      = (const float*)d_in[0];
  const float* grid_pos = (const float*)d_in[1];
  const float* w1 = (const float*)d_in[2];
  const float* b1 = (const float*)d_in[3];
  const float* w2 = (const float*)d_in[4];
  const float* b2 = (const float*)d_in[5];
  const float* w3 = (const float*)d_in[6];
  const float* b3 = (const float*)d_in[7];
  const float* w4 = (const float*)d_in[8];
  const float* b4 = (const float*)d_in[9];
  const float* w5 = (const float*)d_in[10];
  const float* b5 = (const float*)d_in[11];
  const float* w6 = (const float*)d_in[12];
  const float* b6 = (const float*)d_in[13];
  float* out = (float*)d_out;

  prep<<<(303104 + 255) / 256, 256>>>(w2, w3, w4, w5, w6);

  const int B = in_sizes[0] / 2;
  cudaFuncSetAttribute(gridnet_mma, cudaFuncAttributeMaxDynamicSharedMemorySize,
                       SMEM_TOTAL);
  gridnet_mma<<<B / 128, NTH, SMEM_TOTAL>>>(pos, grid_pos, w1, b1, b2, b3, b4,
                                            b5, b6, out);
}